// round 2
// baseline (speedup 1.0000x reference)
#include <cuda_runtime.h>

// Problem constants
#define BSZ   64
#define CC    2048
#define HH    24
#define WW    8
#define LL    192          // H*W
#define DIN2  384
#define DD    192          // Dssm
#define NN    16
#define RR    6
#define MM    (BSZ*LL)     // 12288 rows
#define NPROJ (RR + 2*NN)  // 38

// ---------------- scratch (__device__ globals, no allocation) ----------------
__device__ float g_fm  [(size_t)MM*CC];     // layernormed input  [M, C]
__device__ float g_xz  [(size_t)MM*DIN2];   // in-proj output     [M, 384]
__device__ float g_xdbl[(size_t)MM*NPROJ];  // x_proj output      [M, 38]
__device__ float g_dts [(size_t)MM*DD];     // softplus(dt)       [M, 192]
__device__ float g_ssm [(size_t)MM*DD];     // scan output/gated  [M, 192]
__device__ float g_out1[(size_t)MM*CC];     // out-proj + fm      [M, C]

// ---------------- 1. fused transpose + LayerNorm ----------------
// grid = MM blocks, 256 threads. Each block handles one (b, l) row of C=2048.
__global__ void ln_kernel(const float* __restrict__ x,
                          const float* __restrict__ w,
                          const float* __restrict__ b)
{
    int m  = blockIdx.x;
    int bb = m / LL, l = m % LL;
    const float* src = x + (size_t)bb * CC * LL + l;   // element c at src[c*LL]

    float v[8];
    float s = 0.f, s2 = 0.f;
#pragma unroll
    for (int k = 0; k < 8; k++) {
        int c = threadIdx.x + k * 256;
        float t = src[(size_t)c * LL];
        v[k] = t; s += t; s2 += t * t;
    }

    // block reduce (sum, sumsq)
    __shared__ float sred[64];
#pragma unroll
    for (int o = 16; o > 0; o >>= 1) {
        s  += __shfl_down_sync(0xffffffffu, s,  o);
        s2 += __shfl_down_sync(0xffffffffu, s2, o);
    }
    int wid = threadIdx.x >> 5, lane = threadIdx.x & 31;
    if (lane == 0) { sred[wid] = s; sred[32 + wid] = s2; }
    __syncthreads();
    if (threadIdx.x == 0) {
        float a = 0.f, a2 = 0.f;
#pragma unroll
        for (int i = 0; i < 8; i++) { a += sred[i]; a2 += sred[32 + i]; }
        sred[0] = a; sred[32] = a2;
    }
    __syncthreads();
    s = sred[0]; s2 = sred[32];

    float mu   = s * (1.f / CC);
    float var  = s2 * (1.f / CC) - mu * mu;
    float rstd = rsqrtf(var + 1e-5f);

    float* dst = g_fm + (size_t)m * CC;
#pragma unroll
    for (int k = 0; k < 8; k++) {
        int c = threadIdx.x + k * 256;
        dst[c] = (v[k] - mu) * rstd * w[c] + b[c];
    }
}

// ---------------- 2. generic fp32 NT GEMM: C = A(MxK) * B(NxK)^T ----------------
// 128x128 tile, BK=8, 256 threads, 8x8 micro-tile.
// EPI 0: C = AB^T + bias                       (row-major [M,N])
// EPI 1: C = AB^T + bias + add[m,n]            (row-major [M,N])
// EPI 2: v = AB^T + bias; BN affine + ReLU; write transposed to (B,C,H,W)
template <int EPI>
__global__ void gemm_nt(const float* __restrict__ A, const float* __restrict__ B,
                        const float* __restrict__ bias, const float* __restrict__ add,
                        float* __restrict__ C, int M, int N, int K,
                        const float* __restrict__ bn_rm, const float* __restrict__ bn_rv,
                        const float* __restrict__ bn_w,  const float* __restrict__ bn_b)
{
    __shared__ float As[8][128];
    __shared__ float Bs[8][128];

    int tid  = threadIdx.x;
    int lrow = tid >> 1;             // 0..127
    int lcol = (tid & 1) << 2;       // 0 or 4
    const float* Ap = A + (size_t)(blockIdx.y * 128 + lrow) * K + lcol;
    const float* Bp = B + (size_t)(blockIdx.x * 128 + lrow) * K + lcol;

    int tx = tid & 15;               // n sub-tile
    int ty = tid >> 4;               // m sub-tile

    float acc[8][8];
#pragma unroll
    for (int i = 0; i < 8; i++)
#pragma unroll
        for (int j = 0; j < 8; j++) acc[i][j] = 0.f;

    for (int k0 = 0; k0 < K; k0 += 8) {
        float4 a4 = *(const float4*)(Ap + k0);
        float4 b4 = *(const float4*)(Bp + k0);
        __syncthreads();
        As[lcol + 0][lrow] = a4.x; As[lcol + 1][lrow] = a4.y;
        As[lcol + 2][lrow] = a4.z; As[lcol + 3][lrow] = a4.w;
        Bs[lcol + 0][lrow] = b4.x; Bs[lcol + 1][lrow] = b4.y;
        Bs[lcol + 2][lrow] = b4.z; Bs[lcol + 3][lrow] = b4.w;
        __syncthreads();
#pragma unroll
        for (int k = 0; k < 8; k++) {
            float ar[8], br[8];
            *(float4*)(ar)     = *(const float4*)&As[k][ty * 8];
            *(float4*)(ar + 4) = *(const float4*)&As[k][ty * 8 + 4];
            *(float4*)(br)     = *(const float4*)&Bs[k][tx * 8];
            *(float4*)(br + 4) = *(const float4*)&Bs[k][tx * 8 + 4];
#pragma unroll
            for (int i = 0; i < 8; i++)
#pragma unroll
                for (int j = 0; j < 8; j++)
                    acc[i][j] += ar[i] * br[j];
        }
    }

    int m0 = blockIdx.y * 128 + ty * 8;
    int n0 = blockIdx.x * 128 + tx * 8;
#pragma unroll
    for (int j = 0; j < 8; j++) {
        int n = n0 + j;
        float bi = bias[n];
        float bnw = 0.f, bnb = 0.f, brm = 0.f, rst = 0.f;
        if (EPI == 2) {
            brm = bn_rm[n];
            rst = rsqrtf(bn_rv[n] + 1e-5f);
            bnw = bn_w[n]; bnb = bn_b[n];
        }
#pragma unroll
        for (int i = 0; i < 8; i++) {
            int m = m0 + i;
            float v = acc[i][j] + bi;
            if (EPI == 0) {
                C[(size_t)m * N + n] = v;
            } else if (EPI == 1) {
                C[(size_t)m * N + n] = v + add[(size_t)m * N + n];
            } else {
                v = (v - brm) * rst * bnw + bnb;
                v = fmaxf(v, 0.f);
                int bb = m / LL, l = m % LL;
                C[((size_t)bb * CC + n) * LL + l] = v;   // (B,C,H,W) layout
            }
        }
    }
}

// ---------------- 3. x_proj: x_dbl[m, j] = dot(x[m,:192], x_proj_w[j,:]) ----------------
__global__ void xproj_kernel(const float* __restrict__ xpw)
{
    int idx = blockIdx.x * blockDim.x + threadIdx.x;
    if (idx >= MM * NPROJ) return;
    int m = idx / NPROJ, j = idx % NPROJ;
    const float* xr = g_xz + (size_t)m * DIN2;   // x part = first 192
    const float* wr = xpw + j * DD;
    float acc = 0.f;
#pragma unroll 8
    for (int k = 0; k < DD; k++) acc += xr[k] * wr[k];
    g_xdbl[idx] = acc;
}

// ---------------- 4. dts = softplus(x_dbl[:, :6] @ dt_w^T) ----------------
__global__ void dt_kernel(const float* __restrict__ dtw)
{
    int idx = blockIdx.x * blockDim.x + threadIdx.x;
    if (idx >= MM * DD) return;
    int m = idx / DD, d = idx % DD;
    const float* xd = g_xdbl + (size_t)m * NPROJ;
    float acc = 0.f;
#pragma unroll
    for (int r = 0; r < RR; r++) acc += xd[r] * dtw[d * RR + r];
    float sp = (acc > 20.f) ? acc : log1pf(__expf(acc));
    g_dts[idx] = sp;
}

// ---------------- 5. bidirectional selective scan + gate ----------------
// grid = BSZ blocks, DD=192 threads (one per channel d).
__global__ void scan_kernel(const float* __restrict__ A_logs,
                            const float* __restrict__ Ds)
{
    __shared__ float sB[LL][NN];
    __shared__ float sC[LL][NN];
    int b = blockIdx.x, d = threadIdx.x;

    // stage Bs/Cs for this batch into smem (broadcast reads later)
    for (int i = d; i < LL * 2 * NN; i += LL) {
        int l = i >> 5, j = i & 31;
        float v = g_xdbl[((size_t)(b * LL + l)) * NPROJ + RR + j];
        if (j < NN) sB[l][j] = v;
        else        sC[l][j - NN] = v;
    }
    __syncthreads();

    float Ar[NN];
#pragma unroll
    for (int n = 0; n < NN; n++) Ar[n] = -expf(A_logs[d * NN + n]);
    float Dd = Ds[d];

    float u[NN];
#pragma unroll
    for (int n = 0; n < NN; n++) u[n] = 0.f;

    // forward scan
    for (int l = 0; l < LL; l++) {
        int m = b * LL + l;
        float dt = g_dts[(size_t)m * DD + d];
        float xv = g_xz [(size_t)m * DIN2 + d];
        float y = 0.f;
#pragma unroll
        for (int n = 0; n < NN; n++) {
            float a = __expf(dt * Ar[n]);
            u[n] = a * u[n] + dt * sB[l][n] * xv;
            y += u[n] * sC[l][n];
        }
        g_ssm[(size_t)m * DD + d] = y + Dd * xv;
    }

    // backward scan + skip + SiLU gate
#pragma unroll
    for (int n = 0; n < NN; n++) u[n] = 0.f;
    for (int l = LL - 1; l >= 0; l--) {
        int m = b * LL + l;
        float dt = g_dts[(size_t)m * DD + d];
        float xv = g_xz [(size_t)m * DIN2 + d];
        float y = 0.f;
#pragma unroll
        for (int n = 0; n < NN; n++) {
            float a = __expf(dt * Ar[n]);
            u[n] = a * u[n] + dt * sB[l][n] * xv;
            y += u[n] * sC[l][n];
        }
        float tot = g_ssm[(size_t)m * DD + d] + y + Dd * xv;
        float z = g_xz[(size_t)m * DIN2 + DD + d];
        float sig = 1.f / (1.f + __expf(-z));
        g_ssm[(size_t)m * DD + d] = tot * (z * sig);
    }
}

// ---------------- launch ----------------
extern "C" void kernel_launch(void* const* d_in, const int* in_sizes, int n_in,
                              void* d_out, int out_size)
{
    const float* feat_map = (const float*)d_in[0];
    const float* ln_w     = (const float*)d_in[1];
    const float* ln_b     = (const float*)d_in[2];
    const float* in_w     = (const float*)d_in[3];
    const float* in_b     = (const float*)d_in[4];
    const float* x_proj_w = (const float*)d_in[5];
    const float* dt_w     = (const float*)d_in[6];
    const float* A_logs   = (const float*)d_in[7];
    const float* Ds       = (const float*)d_in[8];
    const float* out_w    = (const float*)d_in[9];
    const float* out_b    = (const float*)d_in[10];
    const float* mo_w     = (const float*)d_in[11];
    const float* mo_b     = (const float*)d_in[12];
    const float* bn_w     = (const float*)d_in[13];
    const float* bn_b     = (const float*)d_in[14];
    const float* bn_rm    = (const float*)d_in[15];
    const float* bn_rv    = (const float*)d_in[16];
    float* out = (float*)d_out;

    float *fm, *xz, *ssm, *out1;
    cudaGetSymbolAddress((void**)&fm,   g_fm);
    cudaGetSymbolAddress((void**)&xz,   g_xz);
    cudaGetSymbolAddress((void**)&ssm,  g_ssm);
    cudaGetSymbolAddress((void**)&out1, g_out1);

    // 1. transpose + LayerNorm
    ln_kernel<<<MM, 256>>>(feat_map, ln_w, ln_b);

    // 2. in-projection: xz[M,384] = fm[M,2048] @ in_w[384,2048]^T + in_b
    gemm_nt<0><<<dim3(DIN2 / 128, MM / 128), 256>>>(
        fm, in_w, in_b, nullptr, xz, MM, DIN2, CC,
        nullptr, nullptr, nullptr, nullptr);

    // 3. x-proj (38 outputs) and dt softplus
    xproj_kernel<<<(MM * NPROJ) / 256, 256>>>(x_proj_w);
    dt_kernel<<<(MM * DD) / 256, 256>>>(dt_w);

    // 4. bidirectional scan + gate
    scan_kernel<<<BSZ, DD>>>(A_logs, Ds);

    // 5. out-projection + residual: out1[M,2048] = ssm[M,192] @ out_w^T + out_b + fm
    gemm_nt<1><<<dim3(CC / 128, MM / 128), 256>>>(
        ssm, out_w, out_b, fm, out1, MM, CC, DD,
        nullptr, nullptr, nullptr, nullptr);

    // 6. mixer GEMM + BN + ReLU + transposed write to (B,C,H,W)
    gemm_nt<2><<<dim3(CC / 128, MM / 128), 256>>>(
        out1, mo_w, mo_b, nullptr, out, MM, CC, CC,
        bn_rm, bn_rv, bn_w, bn_b);
}

// round 7
// speedup vs baseline: 1.4644x; 1.4644x over previous
#include <cuda_runtime.h>
#include <cuda_bf16.h>
#include <cstdint>

// ---------------- problem constants ----------------
#define BSZ   64
#define CC    2048
#define LL    192
#define DIN2  384
#define DD    192
#define NN    16
#define RR    6
#define MM    (BSZ*LL)     // 12288
#define NPROJ 38
#define KIN   (3*CC)       // 6144
#define KOUT  (3*DD)       // 576

// ---------------- scratch ----------------
__device__ float g_xz  [(size_t)MM*DIN2];
__device__ float g_xdbl[(size_t)MM*NPROJ];
__device__ float g_dts [(size_t)MM*DD];
__device__ float g_ssm [(size_t)MM*DD];
__device__ __align__(128) __nv_bfloat16 g_fm_e  [(size_t)MM*KIN];
__device__ __align__(128) __nv_bfloat16 g_out1_e[(size_t)MM*KIN];
__device__ __align__(128) __nv_bfloat16 g_ssm_e [(size_t)MM*KOUT];
__device__ __align__(128) __nv_bfloat16 g_inw_e [(size_t)DIN2*KIN];
__device__ __align__(128) __nv_bfloat16 g_outw_e[(size_t)CC*KOUT];
__device__ __align__(128) __nv_bfloat16 g_mow_e [(size_t)CC*KIN];

// ---------------- helpers ----------------
__device__ __forceinline__ uint32_t smem_to_u32(const void* p) {
    uint32_t a;
    asm("{ .reg .u64 t; cvta.to.shared.u64 t, %1; cvt.u32.u64 %0, t; }" : "=r"(a) : "l"(p));
    return a;
}
#define SMEM_SWIZZLE_128B(off) ((off) ^ (((off) >> 3) & 0x70))

__device__ __forceinline__ uint32_t lds32(uint32_t a) {
    uint32_t v;
    asm volatile("ld.shared.b32 %0, [%1];" : "=r"(v) : "r"(a));
    return v;
}

#define CP_ASYNC16(smem_u32, gptr) \
    asm volatile("cp.async.cg.shared.global [%0], [%1], 16;" \
                 :: "r"(smem_u32), "l"(__cvta_generic_to_global((const void*)(gptr))) : "memory")
#define CP_ASYNC_COMMIT() asm volatile("cp.async.commit_group;" ::: "memory")
#define CP_ASYNC_WAIT_0() asm volatile("cp.async.wait_group 0;" ::: "memory")

#define MMA_BF16(d, a, b) \
    asm volatile("mma.sync.aligned.m16n8k16.row.col.f32.bf16.bf16.f32 " \
                 "{%0,%1,%2,%3}, {%4,%5,%6,%7}, {%8,%9}, {%0,%1,%2,%3};" \
                 : "+f"((d)[0]), "+f"((d)[1]), "+f"((d)[2]), "+f"((d)[3]) \
                 : "r"((a)[0]), "r"((a)[1]), "r"((a)[2]), "r"((a)[3]), \
                   "r"((b)[0]), "r"((b)[1]))

// ---------------- split-bf16 helpers ----------------
// Activations (A operand):  [hi, lo, hi]
// Weights     (B operand):  [hi, hi, lo]
// K'-dot = Ah*Bh + Al*Bh + Ah*Bl  (drops only Al*Bl ~ 2^-16 relative)
__device__ __forceinline__ void split3a(float v, __nv_bfloat16* row, int K, int c) {
    __nv_bfloat16 h = __float2bfloat16(v);
    float lo = v - __bfloat162float(h);
    row[c] = h;
    row[K + c] = __float2bfloat16(lo);
    row[2 * K + c] = h;
}
__device__ __forceinline__ void split3w(float v, __nv_bfloat16* row, int K, int c) {
    __nv_bfloat16 h = __float2bfloat16(v);
    float lo = v - __bfloat162float(h);
    row[c] = h;
    row[K + c] = h;
    row[2 * K + c] = __float2bfloat16(lo);
}

// ---------------- 1. transpose + LayerNorm -> split-bf16 fm (activation layout) ----------------
__global__ void ln_kernel(const float* __restrict__ x,
                          const float* __restrict__ w,
                          const float* __restrict__ b)
{
    int m  = blockIdx.x;
    int bb = m / LL, l = m % LL;
    const float* src = x + (size_t)bb * CC * LL + l;

    float v[8];
    float s = 0.f, s2 = 0.f;
#pragma unroll
    for (int k = 0; k < 8; k++) {
        int c = threadIdx.x + k * 256;
        float t = src[(size_t)c * LL];
        v[k] = t; s += t; s2 += t * t;
    }
    __shared__ float sred[64];
#pragma unroll
    for (int o = 16; o > 0; o >>= 1) {
        s  += __shfl_down_sync(0xffffffffu, s,  o);
        s2 += __shfl_down_sync(0xffffffffu, s2, o);
    }
    int wid = threadIdx.x >> 5, lane = threadIdx.x & 31;
    if (lane == 0) { sred[wid] = s; sred[32 + wid] = s2; }
    __syncthreads();
    if (threadIdx.x == 0) {
        float a = 0.f, a2 = 0.f;
#pragma unroll
        for (int i = 0; i < 8; i++) { a += sred[i]; a2 += sred[32 + i]; }
        sred[0] = a; sred[32] = a2;
    }
    __syncthreads();
    s = sred[0]; s2 = sred[32];

    float mu   = s * (1.f / CC);
    float var  = s2 * (1.f / CC) - mu * mu;
    float rstd = rsqrtf(var + 1e-5f);

    __nv_bfloat16* dst = g_fm_e + (size_t)m * KIN;
#pragma unroll
    for (int k = 0; k < 8; k++) {
        int c = threadIdx.x + k * 256;
        float fv = (v[k] - mu) * rstd * w[c] + b[c];
        split3a(fv, dst, CC, c);
    }
}

// ---------------- weight split-convert: fp32 [N,K] -> bf16 [N,3K] weight layout ----------------
__global__ void wconv_kernel(const float* __restrict__ w, __nv_bfloat16* __restrict__ o,
                             int K, int total)
{
    int idx = blockIdx.x * blockDim.x + threadIdx.x;
    if (idx >= total) return;
    int r = idx / K, c = idx % K;
    split3w(w[idx], o + (size_t)r * 3 * K, K, c);
}

// ---------------- mma.sync bf16 GEMM: C = A(M x K') * B(N x K')^T ----------------
// 128x128 block, BK=64, 2-stage cp.async double buffer, 8 warps (2m x 4n).
template <int EPI>
__global__ void __launch_bounds__(256, 2) gemm_mma(
    const __nv_bfloat16* __restrict__ A, const __nv_bfloat16* __restrict__ B,
    int K, int Nout,
    const float* __restrict__ bias,
    const __nv_bfloat16* __restrict__ resid,
    float* __restrict__ Cf, __nv_bfloat16* __restrict__ Cb,
    const float* __restrict__ bn_rm, const float* __restrict__ bn_rv,
    const float* __restrict__ bn_w,  const float* __restrict__ bn_b)
{
    constexpr int ABYTES = 128 * 128;    // 128 rows x 64 bf16
    constexpr int STAGE  = 2 * ABYTES;   // A + B

    extern __shared__ char smem[];
    uint32_t sb = smem_to_u32(smem);

    int tid = threadIdx.x, wid = tid >> 5, lane = tid & 31;
    int m0 = blockIdx.y * 128, n0 = blockIdx.x * 128;
    int wm0 = (wid & 1) * 64;            // warp m offset
    int wn0 = (wid >> 1) * 32;           // warp n offset

    int r4 = lane >> 2;                  // fragment row/col group
    int kb = (lane & 3) * 4;             // byte offset of this thread's k-pair

    float acc[4][4][4];
#pragma unroll
    for (int i = 0; i < 4; i++)
#pragma unroll
        for (int j = 0; j < 4; j++)
#pragma unroll
            for (int q = 0; q < 4; q++) acc[i][j][q] = 0.f;

    const int T = K / 64;

    int lrow = tid >> 3;                 // 0..31
    int lcol = tid & 7;                  // 16B chunk col
    auto load = [&](int j) {
        uint32_t abase = sb + (j & 1) * STAGE;
        uint32_t bbase = abase + ABYTES;
        int k0 = j * 64;
#pragma unroll
        for (int c = 0; c < 4; c++) {
            int row = lrow + c * 32;
            uint32_t soff = SMEM_SWIZZLE_128B((uint32_t)(row * 128 + lcol * 16));
            CP_ASYNC16(abase + soff, A + (size_t)(m0 + row) * K + k0 + lcol * 8);
            CP_ASYNC16(bbase + soff, B + (size_t)(n0 + row) * K + k0 + lcol * 8);
        }
    };

    load(0); CP_ASYNC_COMMIT();

    for (int i = 0; i < T; i++) {
        CP_ASYNC_WAIT_0();
        __syncthreads();

        if (i + 1 < T) { load(i + 1); CP_ASYNC_COMMIT(); }

        uint32_t abase = sb + (i & 1) * STAGE;
        uint32_t bbase = abase + ABYTES;

#pragma unroll
        for (int kk = 0; kk < 4; kk++) {
            int kbyte = kk * 32 + kb;            // byte col of k-pair in 128B row
            uint32_t a[4][4], bf[4][2];
#pragma unroll
            for (int mi = 0; mi < 4; mi++) {
                int r = wm0 + mi * 16 + r4;
                a[mi][0] = lds32(abase + SMEM_SWIZZLE_128B((uint32_t)(r * 128 + kbyte)));
                a[mi][1] = lds32(abase + SMEM_SWIZZLE_128B((uint32_t)((r + 8) * 128 + kbyte)));
                a[mi][2] = lds32(abase + SMEM_SWIZZLE_128B((uint32_t)(r * 128 + kbyte + 16)));
                a[mi][3] = lds32(abase + SMEM_SWIZZLE_128B((uint32_t)((r + 8) * 128 + kbyte + 16)));
            }
#pragma unroll
            for (int ni = 0; ni < 4; ni++) {
                int n = wn0 + ni * 8 + r4;
                bf[ni][0] = lds32(bbase + SMEM_SWIZZLE_128B((uint32_t)(n * 128 + kbyte)));
                bf[ni][1] = lds32(bbase + SMEM_SWIZZLE_128B((uint32_t)(n * 128 + kbyte + 16)));
            }
#pragma unroll
            for (int mi = 0; mi < 4; mi++)
#pragma unroll
                for (int ni = 0; ni < 4; ni++)
                    MMA_BF16(acc[mi][ni], a[mi], bf[ni]);
        }
        __syncthreads();
    }

    // ---------------- epilogue ----------------
    int qrow = lane >> 2;
    int qcol = (lane & 3) * 2;
#pragma unroll
    for (int mi = 0; mi < 4; mi++) {
#pragma unroll
        for (int ni = 0; ni < 4; ni++) {
#pragma unroll
            for (int h = 0; h < 2; h++) {
#pragma unroll
                for (int q = 0; q < 2; q++) {
                    int m = m0 + wm0 + mi * 16 + qrow + h * 8;
                    int n = n0 + wn0 + ni * 8 + qcol + q;
                    float v = acc[mi][ni][h * 2 + q] + bias[n];
                    if (EPI == 0) {
                        Cf[(size_t)m * Nout + n] = v;
                    } else if (EPI == 1) {
                        v += __bfloat162float(resid[(size_t)m * KIN + n])
                           + __bfloat162float(resid[(size_t)m * KIN + CC + n]);
                        split3a(v, Cb + (size_t)m * KIN, CC, n);
                    } else {
                        float rs = rsqrtf(bn_rv[n] + 1e-5f);
                        v = (v - bn_rm[n]) * rs * bn_w[n] + bn_b[n];
                        v = fmaxf(v, 0.f);
                        int bb = m / LL, l = m - bb * LL;
                        Cf[((size_t)bb * CC + n) * LL + l] = v;
                    }
                }
            }
        }
    }
}

// ---------------- x_proj ----------------
__global__ void xproj_kernel(const float* __restrict__ xpw)
{
    int idx = blockIdx.x * blockDim.x + threadIdx.x;
    if (idx >= MM * NPROJ) return;
    int m = idx / NPROJ, j = idx % NPROJ;
    const float* xr = g_xz + (size_t)m * DIN2;
    const float* wr = xpw + j * DD;
    float acc = 0.f;
#pragma unroll 8
    for (int k = 0; k < DD; k++) acc += xr[k] * wr[k];
    g_xdbl[idx] = acc;
}

// ---------------- dt softplus ----------------
__global__ void dt_kernel(const float* __restrict__ dtw)
{
    int idx = blockIdx.x * blockDim.x + threadIdx.x;
    if (idx >= MM * DD) return;
    int m = idx / DD, d = idx % DD;
    const float* xd = g_xdbl + (size_t)m * NPROJ;
    float acc = 0.f;
#pragma unroll
    for (int r = 0; r < RR; r++) acc += xd[r] * dtw[d * RR + r];
    float sp = (acc > 20.f) ? acc : log1pf(__expf(acc));
    g_dts[idx] = sp;
}

// ---------------- bidirectional scan + SiLU gate -> split-bf16 ssm (activation layout) ----------------
__global__ void scan_kernel(const float* __restrict__ A_logs,
                            const float* __restrict__ Ds)
{
    __shared__ float sB[LL][NN];
    __shared__ float sC[LL][NN];
    int b = blockIdx.x, d = threadIdx.x;

    for (int i = d; i < LL * 2 * NN; i += LL) {
        int l = i >> 5, j = i & 31;
        float v = g_xdbl[((size_t)(b * LL + l)) * NPROJ + RR + j];
        if (j < NN) sB[l][j] = v;
        else        sC[l][j - NN] = v;
    }
    __syncthreads();

    float Ar[NN];
#pragma unroll
    for (int n = 0; n < NN; n++) Ar[n] = -expf(A_logs[d * NN + n]);
    float Dd = Ds[d];

    float u[NN];
#pragma unroll
    for (int n = 0; n < NN; n++) u[n] = 0.f;

    for (int l = 0; l < LL; l++) {
        int m = b * LL + l;
        float dt = g_dts[(size_t)m * DD + d];
        float xv = g_xz [(size_t)m * DIN2 + d];
        float y = 0.f;
#pragma unroll
        for (int n = 0; n < NN; n++) {
            float a = __expf(dt * Ar[n]);
            u[n] = a * u[n] + dt * sB[l][n] * xv;
            y += u[n] * sC[l][n];
        }
        g_ssm[(size_t)m * DD + d] = y + Dd * xv;
    }

#pragma unroll
    for (int n = 0; n < NN; n++) u[n] = 0.f;
    for (int l = LL - 1; l >= 0; l--) {
        int m = b * LL + l;
        float dt = g_dts[(size_t)m * DD + d];
        float xv = g_xz [(size_t)m * DIN2 + d];
        float y = 0.f;
#pragma unroll
        for (int n = 0; n < NN; n++) {
            float a = __expf(dt * Ar[n]);
            u[n] = a * u[n] + dt * sB[l][n] * xv;
            y += u[n] * sC[l][n];
        }
        float tot = g_ssm[(size_t)m * DD + d] + y + Dd * xv;
        float z = g_xz[(size_t)m * DIN2 + DD + d];
        float sig = 1.f / (1.f + __expf(-z));
        split3a(tot * (z * sig), g_ssm_e + (size_t)m * KOUT, DD, d);
    }
}

// ---------------- launch ----------------
extern "C" void kernel_launch(void* const* d_in, const int* in_sizes, int n_in,
                              void* d_out, int out_size)
{
    const float* feat_map = (const float*)d_in[0];
    const float* ln_w     = (const float*)d_in[1];
    const float* ln_b     = (const float*)d_in[2];
    const float* in_w     = (const float*)d_in[3];
    const float* in_b     = (const float*)d_in[4];
    const float* x_proj_w = (const float*)d_in[5];
    const float* dt_w     = (const float*)d_in[6];
    const float* A_logs   = (const float*)d_in[7];
    const float* Ds       = (const float*)d_in[8];
    const float* out_w    = (const float*)d_in[9];
    const float* out_b    = (const float*)d_in[10];
    const float* mo_w     = (const float*)d_in[11];
    const float* mo_b     = (const float*)d_in[12];
    const float* bn_w     = (const float*)d_in[13];
    const float* bn_b     = (const float*)d_in[14];
    const float* bn_rm    = (const float*)d_in[15];
    const float* bn_rv    = (const float*)d_in[16];
    float* out = (float*)d_out;

    __nv_bfloat16 *fm_e, *out1_e, *ssm_e, *inw_e, *outw_e, *mow_e;
    float *xz;
    cudaGetSymbolAddress((void**)&fm_e,   g_fm_e);
    cudaGetSymbolAddress((void**)&out1_e, g_out1_e);
    cudaGetSymbolAddress((void**)&ssm_e,  g_ssm_e);
    cudaGetSymbolAddress((void**)&inw_e,  g_inw_e);
    cudaGetSymbolAddress((void**)&outw_e, g_outw_e);
    cudaGetSymbolAddress((void**)&mow_e,  g_mow_e);
    cudaGetSymbolAddress((void**)&xz,     g_xz);

    const int SMEM = 2 * 2 * 128 * 128;   // 65536
    cudaFuncSetAttribute(gemm_mma<0>, cudaFuncAttributeMaxDynamicSharedMemorySize, SMEM);
    cudaFuncSetAttribute(gemm_mma<1>, cudaFuncAttributeMaxDynamicSharedMemorySize, SMEM);
    cudaFuncSetAttribute(gemm_mma<2>, cudaFuncAttributeMaxDynamicSharedMemorySize, SMEM);

    // 1. transpose + LN -> fm split-bf16 (activation layout)
    ln_kernel<<<MM, 256>>>(feat_map, ln_w, ln_b);

    // weight conversions (weight layout [h, h, lo])
    wconv_kernel<<<(DIN2 * CC + 255) / 256, 256>>>(in_w,  inw_e,  CC, DIN2 * CC);
    wconv_kernel<<<(CC * DD   + 255) / 256, 256>>>(out_w, outw_e, DD, CC * DD);
    wconv_kernel<<<(CC * CC   + 255) / 256, 256>>>(mo_w,  mow_e,  CC, CC * CC);

    // 2. in-projection: xz = fm @ in_w^T + in_b  (fp32 out)
    gemm_mma<0><<<dim3(DIN2 / 128, MM / 128), 256, SMEM>>>(
        fm_e, inw_e, KIN, DIN2, in_b, nullptr, xz, nullptr,
        nullptr, nullptr, nullptr, nullptr);

    // 3. x-proj + dt
    xproj_kernel<<<(MM * NPROJ + 255) / 256, 256>>>(x_proj_w);
    dt_kernel<<<(MM * DD) / 256, 256>>>(dt_w);

    // 4. scan + gate -> ssm split-bf16 (activation layout)
    scan_kernel<<<BSZ, DD>>>(A_logs, Ds);

    // 5. out-projection + fm residual -> out1 split-bf16 (activation layout)
    gemm_mma<1><<<dim3(CC / 128, MM / 128), 256, SMEM>>>(
        ssm_e, outw_e, KOUT, CC, out_b, fm_e, nullptr, out1_e,
        nullptr, nullptr, nullptr, nullptr);

    // 6. mixer GEMM + BN + ReLU + NCHW write
    gemm_mma<2><<<dim3(CC / 128, MM / 128), 256, SMEM>>>(
        out1_e, mow_e, KIN, CC, mo_b, nullptr, out, nullptr,
        bn_rm, bn_rv, bn_w, bn_b);
}

// round 8
// speedup vs baseline: 1.7057x; 1.1647x over previous
#include <cuda_runtime.h>
#include <cuda_bf16.h>
#include <cstdint>

// ---------------- problem constants ----------------
#define BSZ   64
#define CC    2048
#define LL    192
#define DIN2  384
#define DD    192
#define NN    16
#define RR    6
#define MM    (BSZ*LL)     // 12288
#define NPROJ 38
#define KIN   (3*CC)       // 6144
#define KOUT  (3*DD)       // 576

// ---------------- scratch ----------------
__device__ float g_xz  [(size_t)MM*DIN2];
__device__ float g_xdbl[(size_t)MM*NPROJ];
__device__ float g_dts [(size_t)MM*DD];
__device__ float g_ssm [(size_t)MM*DD];
__device__ __align__(128) __nv_bfloat16 g_fm_e  [(size_t)MM*KIN];
__device__ __align__(128) __nv_bfloat16 g_out1_e[(size_t)MM*KIN];
__device__ __align__(128) __nv_bfloat16 g_ssm_e [(size_t)MM*KOUT];
__device__ __align__(128) __nv_bfloat16 g_inw_e [(size_t)DIN2*KIN];
__device__ __align__(128) __nv_bfloat16 g_outw_e[(size_t)CC*KOUT];
__device__ __align__(128) __nv_bfloat16 g_mow_e [(size_t)CC*KIN];

// ---------------- helpers ----------------
__device__ __forceinline__ uint32_t smem_to_u32(const void* p) {
    uint32_t a;
    asm("{ .reg .u64 t; cvta.to.shared.u64 t, %1; cvt.u32.u64 %0, t; }" : "=r"(a) : "l"(p));
    return a;
}
#define SMEM_SWIZZLE_128B(off) ((off) ^ (((off) >> 3) & 0x70))

#define CP_ASYNC16(smem_u32, gptr) \
    asm volatile("cp.async.cg.shared.global [%0], [%1], 16;" \
                 :: "r"(smem_u32), "l"(__cvta_generic_to_global((const void*)(gptr))) : "memory")
#define CP_ASYNC_COMMIT() asm volatile("cp.async.commit_group;" ::: "memory")
#define CP_ASYNC_WAIT_1() asm volatile("cp.async.wait_group 1;" ::: "memory")

#define LDSM_X4(r0, r1, r2, r3, addr) \
    asm volatile("ldmatrix.sync.aligned.m8n8.x4.shared.b16 {%0,%1,%2,%3}, [%4];" \
                 : "=r"(r0), "=r"(r1), "=r"(r2), "=r"(r3) : "r"(addr))

#define MMA_BF16(d, a, b0, b1) \
    asm volatile("mma.sync.aligned.m16n8k16.row.col.f32.bf16.bf16.f32 " \
                 "{%0,%1,%2,%3}, {%4,%5,%6,%7}, {%8,%9}, {%0,%1,%2,%3};" \
                 : "+f"((d)[0]), "+f"((d)[1]), "+f"((d)[2]), "+f"((d)[3]) \
                 : "r"((a)[0]), "r"((a)[1]), "r"((a)[2]), "r"((a)[3]), \
                   "r"(b0), "r"(b1))

// ---------------- split-bf16 helpers ----------------
// Activations (A operand):  [hi, lo, hi]
// Weights     (B operand):  [hi, hi, lo]
// K'-dot = Ah*Bh + Al*Bh + Ah*Bl  (drops only Al*Bl ~ 2^-18 relative)
__device__ __forceinline__ void split3a(float v, __nv_bfloat16* row, int K, int c) {
    __nv_bfloat16 h = __float2bfloat16(v);
    float lo = v - __bfloat162float(h);
    row[c] = h;
    row[K + c] = __float2bfloat16(lo);
    row[2 * K + c] = h;
}
__device__ __forceinline__ void split3w(float v, __nv_bfloat16* row, int K, int c) {
    __nv_bfloat16 h = __float2bfloat16(v);
    float lo = v - __bfloat162float(h);
    row[c] = h;
    row[K + c] = h;
    row[2 * K + c] = __float2bfloat16(lo);
}

// ---------------- 1. transpose + LayerNorm -> split-bf16 fm ----------------
__global__ void ln_kernel(const float* __restrict__ x,
                          const float* __restrict__ w,
                          const float* __restrict__ b)
{
    int m  = blockIdx.x;
    int bb = m / LL, l = m % LL;
    const float* src = x + (size_t)bb * CC * LL + l;

    float v[8];
    float s = 0.f, s2 = 0.f;
#pragma unroll
    for (int k = 0; k < 8; k++) {
        int c = threadIdx.x + k * 256;
        float t = src[(size_t)c * LL];
        v[k] = t; s += t; s2 += t * t;
    }
    __shared__ float sred[64];
#pragma unroll
    for (int o = 16; o > 0; o >>= 1) {
        s  += __shfl_down_sync(0xffffffffu, s,  o);
        s2 += __shfl_down_sync(0xffffffffu, s2, o);
    }
    int wid = threadIdx.x >> 5, lane = threadIdx.x & 31;
    if (lane == 0) { sred[wid] = s; sred[32 + wid] = s2; }
    __syncthreads();
    if (threadIdx.x == 0) {
        float a = 0.f, a2 = 0.f;
#pragma unroll
        for (int i = 0; i < 8; i++) { a += sred[i]; a2 += sred[32 + i]; }
        sred[0] = a; sred[32] = a2;
    }
    __syncthreads();
    s = sred[0]; s2 = sred[32];

    float mu   = s * (1.f / CC);
    float var  = s2 * (1.f / CC) - mu * mu;
    float rstd = rsqrtf(var + 1e-5f);

    __nv_bfloat16* dst = g_fm_e + (size_t)m * KIN;
#pragma unroll
    for (int k = 0; k < 8; k++) {
        int c = threadIdx.x + k * 256;
        float fv = (v[k] - mu) * rstd * w[c] + b[c];
        split3a(fv, dst, CC, c);
    }
}

// ---------------- weight split-convert ----------------
__global__ void wconv_kernel(const float* __restrict__ w, __nv_bfloat16* __restrict__ o,
                             int K, int total)
{
    int idx = blockIdx.x * blockDim.x + threadIdx.x;
    if (idx >= total) return;
    int r = idx / K, c = idx % K;
    split3w(w[idx], o + (size_t)r * 3 * K, K, c);
}

// ---------------- mma.sync bf16 GEMM: C = A(M x K') * B(N x K')^T ----------------
// 128 x BN block, BK=64, 3-stage cp.async, 8 warps (2m x 4n), warp tile 64 x BN/4.
// ldmatrix fragments (mapping validated: identical results to lds32 path).
template <int BN, int EPI>
__global__ void __launch_bounds__(256) gemm_mma(
    const __nv_bfloat16* __restrict__ A, const __nv_bfloat16* __restrict__ B,
    int K, int Nout,
    const float* __restrict__ bias,
    const __nv_bfloat16* __restrict__ resid,
    float* __restrict__ Cf, __nv_bfloat16* __restrict__ Cb,
    const float* __restrict__ bn_rm, const float* __restrict__ bn_rv,
    const float* __restrict__ bn_w,  const float* __restrict__ bn_b)
{
    constexpr int S      = 3;                 // pipeline stages
    constexpr int ABYTES = 128 * 128;         // 128 rows x 64 bf16
    constexpr int BBYTES = BN * 128;
    constexpr int STAGE  = ABYTES + BBYTES;
    constexpr int NT     = BN / 64;           // 16-row B ldmatrix groups per warp
    constexpr int NI     = BN / 32;           // 8-col mma subtiles per warp

    extern __shared__ char smem[];
    uint32_t sb = smem_to_u32(smem);

    int tid = threadIdx.x, wid = tid >> 5, lane = tid & 31;
    int m0 = blockIdx.y * 128, n0 = blockIdx.x * BN;
    int wm0 = (wid & 1) * 64;                // warp m offset
    int wn0 = (wid >> 1) * (BN / 4);         // warp n offset

    int lrow8 = lane & 7;
    int g     = lane >> 3;                   // ldmatrix 8x8 matrix index
    int mg    = (g & 1) * 8;                 // row offset within 16
    int kg    = (g >> 1) * 8;                // k offset within 16

    float acc[4][NI][4];
#pragma unroll
    for (int i = 0; i < 4; i++)
#pragma unroll
        for (int j = 0; j < NI; j++)
#pragma unroll
            for (int q = 0; q < 4; q++) acc[i][j][q] = 0.f;

    const int T = K / 64;

    int lrow = tid >> 3;                     // 0..31
    int lcol = tid & 7;                      // 16B chunk col
    auto load = [&](int j) {
        uint32_t abase = sb + (j % S) * STAGE;
        uint32_t bbase = abase + ABYTES;
        int k0 = j * 64;
#pragma unroll
        for (int c = 0; c < 4; c++) {
            int row = lrow + c * 32;
            uint32_t soff = SMEM_SWIZZLE_128B((uint32_t)(row * 128 + lcol * 16));
            CP_ASYNC16(abase + soff, A + (size_t)(m0 + row) * K + k0 + lcol * 8);
        }
#pragma unroll
        for (int c = 0; c < BN / 32; c++) {
            int row = lrow + c * 32;
            uint32_t soff = SMEM_SWIZZLE_128B((uint32_t)(row * 128 + lcol * 16));
            CP_ASYNC16(bbase + soff, B + (size_t)(n0 + row) * K + k0 + lcol * 8);
        }
    };

    load(0); CP_ASYNC_COMMIT();
    load(1); CP_ASYNC_COMMIT();

    for (int i = 0; i < T; i++) {
        CP_ASYNC_WAIT_1();                  // stage i ready (<=1 group pending)
        __syncthreads();

        if (i + 2 < T) load(i + 2);
        CP_ASYNC_COMMIT();

        uint32_t abase = sb + (i % S) * STAGE;
        uint32_t bbase = abase + ABYTES;

#pragma unroll
        for (int kk = 0; kk < 4; kk++) {
            int coff = (kk * 16 + kg) * 2;
            uint32_t a[4][4], b[NT][4];
#pragma unroll
            for (int mi = 0; mi < 4; mi++) {
                int row = wm0 + mi * 16 + lrow8 + mg;
                uint32_t ad = abase + SMEM_SWIZZLE_128B((uint32_t)(row * 128 + coff));
                LDSM_X4(a[mi][0], a[mi][1], a[mi][2], a[mi][3], ad);
            }
#pragma unroll
            for (int nt = 0; nt < NT; nt++) {
                int row = wn0 + nt * 16 + lrow8 + mg;
                uint32_t bd = bbase + SMEM_SWIZZLE_128B((uint32_t)(row * 128 + coff));
                LDSM_X4(b[nt][0], b[nt][1], b[nt][2], b[nt][3], bd);
            }
#pragma unroll
            for (int mi = 0; mi < 4; mi++) {
#pragma unroll
                for (int nt = 0; nt < NT; nt++) {
                    MMA_BF16(acc[mi][nt * 2 + 0], a[mi], b[nt][0], b[nt][2]);
                    MMA_BF16(acc[mi][nt * 2 + 1], a[mi], b[nt][1], b[nt][3]);
                }
            }
        }
        __syncthreads();
    }

    // ---------------- epilogue ----------------
    int qrow = lane >> 2;
    int qcol = (lane & 3) * 2;
#pragma unroll
    for (int mi = 0; mi < 4; mi++) {
#pragma unroll
        for (int ni = 0; ni < NI; ni++) {
#pragma unroll
            for (int h = 0; h < 2; h++) {
#pragma unroll
                for (int q = 0; q < 2; q++) {
                    int m = m0 + wm0 + mi * 16 + qrow + h * 8;
                    int n = n0 + wn0 + ni * 8 + qcol + q;
                    float v = acc[mi][ni][h * 2 + q] + bias[n];
                    if (EPI == 0) {
                        Cf[(size_t)m * Nout + n] = v;
                    } else if (EPI == 1) {
                        v += __bfloat162float(resid[(size_t)m * KIN + n])
                           + __bfloat162float(resid[(size_t)m * KIN + CC + n]);
                        split3a(v, Cb + (size_t)m * KIN, CC, n);
                    } else {
                        float rs = rsqrtf(bn_rv[n] + 1e-5f);
                        v = (v - bn_rm[n]) * rs * bn_w[n] + bn_b[n];
                        v = fmaxf(v, 0.f);
                        int bb = m / LL, l = m - bb * LL;
                        Cf[((size_t)bb * CC + n) * LL + l] = v;
                    }
                }
            }
        }
    }
}

// ---------------- x_proj ----------------
__global__ void xproj_kernel(const float* __restrict__ xpw)
{
    int idx = blockIdx.x * blockDim.x + threadIdx.x;
    if (idx >= MM * NPROJ) return;
    int m = idx / NPROJ, j = idx % NPROJ;
    const float* xr = g_xz + (size_t)m * DIN2;
    const float* wr = xpw + j * DD;
    float acc = 0.f;
#pragma unroll 8
    for (int k = 0; k < DD; k++) acc += xr[k] * wr[k];
    g_xdbl[idx] = acc;
}

// ---------------- dt softplus ----------------
__global__ void dt_kernel(const float* __restrict__ dtw)
{
    int idx = blockIdx.x * blockDim.x + threadIdx.x;
    if (idx >= MM * DD) return;
    int m = idx / DD, d = idx % DD;
    const float* xd = g_xdbl + (size_t)m * NPROJ;
    float acc = 0.f;
#pragma unroll
    for (int r = 0; r < RR; r++) acc += xd[r] * dtw[d * RR + r];
    float sp = (acc > 20.f) ? acc : log1pf(__expf(acc));
    g_dts[idx] = sp;
}

// ---------------- bidirectional scan + SiLU gate -> split-bf16 ssm ----------------
__global__ void scan_kernel(const float* __restrict__ A_logs,
                            const float* __restrict__ Ds)
{
    __shared__ float sB[LL][NN];
    __shared__ float sC[LL][NN];
    int b = blockIdx.x, d = threadIdx.x;

    for (int i = d; i < LL * 2 * NN; i += LL) {
        int l = i >> 5, j = i & 31;
        float v = g_xdbl[((size_t)(b * LL + l)) * NPROJ + RR + j];
        if (j < NN) sB[l][j] = v;
        else        sC[l][j - NN] = v;
    }
    __syncthreads();

    float Ar[NN];
#pragma unroll
    for (int n = 0; n < NN; n++) Ar[n] = -expf(A_logs[d * NN + n]);
    float Dd = Ds[d];

    float u[NN];
#pragma unroll
    for (int n = 0; n < NN; n++) u[n] = 0.f;

    for (int l = 0; l < LL; l++) {
        int m = b * LL + l;
        float dt = g_dts[(size_t)m * DD + d];
        float xv = g_xz [(size_t)m * DIN2 + d];
        float y = 0.f;
#pragma unroll
        for (int n = 0; n < NN; n++) {
            float a = __expf(dt * Ar[n]);
            u[n] = a * u[n] + dt * sB[l][n] * xv;
            y += u[n] * sC[l][n];
        }
        g_ssm[(size_t)m * DD + d] = y + Dd * xv;
    }

#pragma unroll
    for (int n = 0; n < NN; n++) u[n] = 0.f;
    for (int l = LL - 1; l >= 0; l--) {
        int m = b * LL + l;
        float dt = g_dts[(size_t)m * DD + d];
        float xv = g_xz [(size_t)m * DIN2 + d];
        float y = 0.f;
#pragma unroll
        for (int n = 0; n < NN; n++) {
            float a = __expf(dt * Ar[n]);
            u[n] = a * u[n] + dt * sB[l][n] * xv;
            y += u[n] * sC[l][n];
        }
        float tot = g_ssm[(size_t)m * DD + d] + y + Dd * xv;
        float z = g_xz[(size_t)m * DIN2 + DD + d];
        float sig = 1.f / (1.f + __expf(-z));
        split3a(tot * (z * sig), g_ssm_e + (size_t)m * KOUT, DD, d);
    }
}

// ---------------- launch ----------------
extern "C" void kernel_launch(void* const* d_in, const int* in_sizes, int n_in,
                              void* d_out, int out_size)
{
    const float* feat_map = (const float*)d_in[0];
    const float* ln_w     = (const float*)d_in[1];
    const float* ln_b     = (const float*)d_in[2];
    const float* in_w     = (const float*)d_in[3];
    const float* in_b     = (const float*)d_in[4];
    const float* x_proj_w = (const float*)d_in[5];
    const float* dt_w     = (const float*)d_in[6];
    const float* A_logs   = (const float*)d_in[7];
    const float* Ds       = (const float*)d_in[8];
    const float* out_w    = (const float*)d_in[9];
    const float* out_b    = (const float*)d_in[10];
    const float* mo_w     = (const float*)d_in[11];
    const float* mo_b     = (const float*)d_in[12];
    const float* bn_w     = (const float*)d_in[13];
    const float* bn_b     = (const float*)d_in[14];
    const float* bn_rm    = (const float*)d_in[15];
    const float* bn_rv    = (const float*)d_in[16];
    float* out = (float*)d_out;

    __nv_bfloat16 *fm_e, *out1_e, *ssm_e, *inw_e, *outw_e, *mow_e;
    float *xz;
    cudaGetSymbolAddress((void**)&fm_e,   g_fm_e);
    cudaGetSymbolAddress((void**)&out1_e, g_out1_e);
    cudaGetSymbolAddress((void**)&ssm_e,  g_ssm_e);
    cudaGetSymbolAddress((void**)&inw_e,  g_inw_e);
    cudaGetSymbolAddress((void**)&outw_e, g_outw_e);
    cudaGetSymbolAddress((void**)&mow_e,  g_mow_e);
    cudaGetSymbolAddress((void**)&xz,     g_xz);

    const int SMEM128 = 3 * (128 + 128) * 128;   // 98304
    const int SMEM256 = 3 * (128 + 256) * 128;   // 147456
    cudaFuncSetAttribute(gemm_mma<128, 0>, cudaFuncAttributeMaxDynamicSharedMemorySize, SMEM128);
    cudaFuncSetAttribute(gemm_mma<256, 1>, cudaFuncAttributeMaxDynamicSharedMemorySize, SMEM256);
    cudaFuncSetAttribute(gemm_mma<256, 2>, cudaFuncAttributeMaxDynamicSharedMemorySize, SMEM256);

    // 1. transpose + LN -> fm split-bf16 (activation layout)
    ln_kernel<<<MM, 256>>>(feat_map, ln_w, ln_b);

    // weight conversions (weight layout [h, h, lo])
    wconv_kernel<<<(DIN2 * CC + 255) / 256, 256>>>(in_w,  inw_e,  CC, DIN2 * CC);
    wconv_kernel<<<(CC * DD   + 255) / 256, 256>>>(out_w, outw_e, DD, CC * DD);
    wconv_kernel<<<(CC * CC   + 255) / 256, 256>>>(mo_w,  mow_e,  CC, CC * CC);

    // 2. in-projection: xz = fm @ in_w^T + in_b  (fp32 out)
    gemm_mma<128, 0><<<dim3(DIN2 / 128, MM / 128), 256, SMEM128>>>(
        fm_e, inw_e, KIN, DIN2, in_b, nullptr, xz, nullptr,
        nullptr, nullptr, nullptr, nullptr);

    // 3. x-proj + dt
    xproj_kernel<<<(MM * NPROJ + 255) / 256, 256>>>(x_proj_w);
    dt_kernel<<<(MM * DD) / 256, 256>>>(dt_w);

    // 4. scan + gate -> ssm split-bf16 (activation layout)
    scan_kernel<<<BSZ, DD>>>(A_logs, Ds);

    // 5. out-projection + fm residual -> out1 split-bf16 (activation layout)
    gemm_mma<256, 1><<<dim3(CC / 256, MM / 128), 256, SMEM256>>>(
        ssm_e, outw_e, KOUT, CC, out_b, fm_e, nullptr, out1_e,
        nullptr, nullptr, nullptr, nullptr);

    // 6. mixer GEMM + BN + ReLU + NCHW write
    gemm_mma<256, 2><<<dim3(CC / 256, MM / 128), 256, SMEM256>>>(
        out1_e, mow_e, KIN, CC, mo_b, nullptr, out, nullptr,
        bn_rm, bn_rv, bn_w, bn_b);
}

// round 10
// speedup vs baseline: 1.7785x; 1.0427x over previous
#include <cuda_runtime.h>
#include <cuda_bf16.h>
#include <cstdint>

// ---------------- problem constants ----------------
#define BSZ   64
#define CC    2048
#define LL    192
#define DIN2  384
#define DD    192
#define NN    16
#define RR    6
#define MM    (BSZ*LL)     // 12288
#define NPROJ 38
#define KIN   (3*CC)       // 6144
#define KOUT  (3*DD)       // 576

// ---------------- scratch ----------------
__device__ float g_xz  [(size_t)MM*DIN2];
__device__ float g_xdbl[(size_t)MM*NPROJ];
__device__ float g_dts [(size_t)MM*DD];
__device__ float g_ssm [(size_t)MM*DD];
__device__ __align__(128) __nv_bfloat16 g_fm_e  [(size_t)MM*KIN];
__device__ __align__(128) __nv_bfloat16 g_out1_e[(size_t)MM*KIN];
__device__ __align__(128) __nv_bfloat16 g_ssm_e [(size_t)MM*KOUT];
__device__ __align__(128) __nv_bfloat16 g_inw_e [(size_t)DIN2*KIN];
__device__ __align__(128) __nv_bfloat16 g_outw_e[(size_t)CC*KOUT];
__device__ __align__(128) __nv_bfloat16 g_mow_e [(size_t)CC*KIN];

// ---------------- helpers ----------------
__device__ __forceinline__ uint32_t smem_to_u32(const void* p) {
    uint32_t a;
    asm("{ .reg .u64 t; cvta.to.shared.u64 t, %1; cvt.u32.u64 %0, t; }" : "=r"(a) : "l"(p));
    return a;
}
#define SMEM_SWIZZLE_128B(off) ((off) ^ (((off) >> 3) & 0x70))

#define CP_ASYNC16(smem_u32, gptr) \
    asm volatile("cp.async.cg.shared.global [%0], [%1], 16;" \
                 :: "r"(smem_u32), "l"(__cvta_generic_to_global((const void*)(gptr))) : "memory")
#define CP_ASYNC_COMMIT() asm volatile("cp.async.commit_group;" ::: "memory")
#define CP_ASYNC_WAIT_2() asm volatile("cp.async.wait_group 2;" ::: "memory")

#define LDSM_X4(r0, r1, r2, r3, addr) \
    asm volatile("ldmatrix.sync.aligned.m8n8.x4.shared.b16 {%0,%1,%2,%3}, [%4];" \
                 : "=r"(r0), "=r"(r1), "=r"(r2), "=r"(r3) : "r"(addr))

#define MMA_BF16(d, a, b0, b1) \
    asm volatile("mma.sync.aligned.m16n8k16.row.col.f32.bf16.bf16.f32 " \
                 "{%0,%1,%2,%3}, {%4,%5,%6,%7}, {%8,%9}, {%0,%1,%2,%3};" \
                 : "+f"((d)[0]), "+f"((d)[1]), "+f"((d)[2]), "+f"((d)[3]) \
                 : "r"((a)[0]), "r"((a)[1]), "r"((a)[2]), "r"((a)[3]), \
                   "r"(b0), "r"(b1))

// ---------------- split-bf16 helpers ----------------
// Activations (A operand):  [hi, lo, hi]
// Weights     (B operand):  [hi, hi, lo]
// K'-dot = Ah*Bh + Al*Bh + Ah*Bl  (drops only Al*Bl ~ 2^-18 relative)
__device__ __forceinline__ void split3a(float v, __nv_bfloat16* row, int K, int c) {
    __nv_bfloat16 h = __float2bfloat16(v);
    float lo = v - __bfloat162float(h);
    row[c] = h;
    row[K + c] = __float2bfloat16(lo);
    row[2 * K + c] = h;
}
__device__ __forceinline__ void split3w(float v, __nv_bfloat16* row, int K, int c) {
    __nv_bfloat16 h = __float2bfloat16(v);
    float lo = v - __bfloat162float(h);
    row[c] = h;
    row[K + c] = h;
    row[2 * K + c] = __float2bfloat16(lo);
}

// ---------------- 1. transpose + LayerNorm -> split-bf16 fm ----------------
__global__ void ln_kernel(const float* __restrict__ x,
                          const float* __restrict__ w,
                          const float* __restrict__ b)
{
    int m  = blockIdx.x;
    int bb = m / LL, l = m % LL;
    const float* src = x + (size_t)bb * CC * LL + l;

    float v[8];
    float s = 0.f, s2 = 0.f;
#pragma unroll
    for (int k = 0; k < 8; k++) {
        int c = threadIdx.x + k * 256;
        float t = src[(size_t)c * LL];
        v[k] = t; s += t; s2 += t * t;
    }
    __shared__ float sred[64];
#pragma unroll
    for (int o = 16; o > 0; o >>= 1) {
        s  += __shfl_down_sync(0xffffffffu, s,  o);
        s2 += __shfl_down_sync(0xffffffffu, s2, o);
    }
    int wid = threadIdx.x >> 5, lane = threadIdx.x & 31;
    if (lane == 0) { sred[wid] = s; sred[32 + wid] = s2; }
    __syncthreads();
    if (threadIdx.x == 0) {
        float a = 0.f, a2 = 0.f;
#pragma unroll
        for (int i = 0; i < 8; i++) { a += sred[i]; a2 += sred[32 + i]; }
        sred[0] = a; sred[32] = a2;
    }
    __syncthreads();
    s = sred[0]; s2 = sred[32];

    float mu   = s * (1.f / CC);
    float var  = s2 * (1.f / CC) - mu * mu;
    float rstd = rsqrtf(var + 1e-5f);

    __nv_bfloat16* dst = g_fm_e + (size_t)m * KIN;
#pragma unroll
    for (int k = 0; k < 8; k++) {
        int c = threadIdx.x + k * 256;
        float fv = (v[k] - mu) * rstd * w[c] + b[c];
        split3a(fv, dst, CC, c);
    }
}

// ---------------- weight split-convert ----------------
__global__ void wconv_kernel(const float* __restrict__ w, __nv_bfloat16* __restrict__ o,
                             int K, int total)
{
    int idx = blockIdx.x * blockDim.x + threadIdx.x;
    if (idx >= total) return;
    int r = idx / K, c = idx % K;
    split3w(w[idx], o + (size_t)r * 3 * K, K, c);
}

// ---------------- mma.sync bf16 GEMM: C = A(M x K') * B(N x K')^T ----------------
// 128 x BN block, BK=64, 4-stage cp.async (distance 2), ONE sync per iter,
// 8 warps (2m x 4n), warp tile 64 x BN/4, ldmatrix fragments.
template <int BN, int EPI>
__global__ void __launch_bounds__(256) gemm_mma(
    const __nv_bfloat16* __restrict__ A, const __nv_bfloat16* __restrict__ B,
    int K, int Nout,
    const float* __restrict__ bias,
    const __nv_bfloat16* __restrict__ resid,
    float* __restrict__ Cf, __nv_bfloat16* __restrict__ Cb,
    const float* __restrict__ bn_rm, const float* __restrict__ bn_rv,
    const float* __restrict__ bn_w,  const float* __restrict__ bn_b)
{
    constexpr int S      = 4;                 // pipeline stages
    constexpr int ABYTES = 128 * 128;         // 128 rows x 64 bf16
    constexpr int BBYTES = BN * 128;
    constexpr int STAGE  = ABYTES + BBYTES;
    constexpr int NT     = BN / 64;           // 16-row B ldmatrix groups per warp
    constexpr int NI     = BN / 32;           // 8-col mma subtiles per warp

    extern __shared__ char smem[];
    uint32_t sb = smem_to_u32(smem);

    int tid = threadIdx.x, wid = tid >> 5, lane = tid & 31;
    int m0 = blockIdx.y * 128, n0 = blockIdx.x * BN;
    int wm0 = (wid & 1) * 64;                // warp m offset
    int wn0 = (wid >> 1) * (BN / 4);         // warp n offset

    int lrow8 = lane & 7;
    int g     = lane >> 3;                   // ldmatrix 8x8 matrix index
    int mg    = (g & 1) * 8;                 // row offset within 16
    int kg    = (g >> 1) * 8;                // k offset within 16

    float acc[4][NI][4];
#pragma unroll
    for (int i = 0; i < 4; i++)
#pragma unroll
        for (int j = 0; j < NI; j++)
#pragma unroll
            for (int q = 0; q < 4; q++) acc[i][j][q] = 0.f;

    const int T = K / 64;

    int lrow = tid >> 3;                     // 0..31
    int lcol = tid & 7;                      // 16B chunk col
    auto load = [&](int j) {
        uint32_t abase = sb + (j % S) * STAGE;
        uint32_t bbase = abase + ABYTES;
        int k0 = j * 64;
#pragma unroll
        for (int c = 0; c < 4; c++) {
            int row = lrow + c * 32;
            uint32_t soff = SMEM_SWIZZLE_128B((uint32_t)(row * 128 + lcol * 16));
            CP_ASYNC16(abase + soff, A + (size_t)(m0 + row) * K + k0 + lcol * 8);
        }
#pragma unroll
        for (int c = 0; c < BN / 32; c++) {
            int row = lrow + c * 32;
            uint32_t soff = SMEM_SWIZZLE_128B((uint32_t)(row * 128 + lcol * 16));
            CP_ASYNC16(bbase + soff, B + (size_t)(n0 + row) * K + k0 + lcol * 8);
        }
    };

    load(0); CP_ASYNC_COMMIT();
    load(1); CP_ASYNC_COMMIT();

    for (int i = 0; i < T; i++) {
        // prefetch first, then wait for stage i: pending {i, i+1, i+2} -> wait<=2
        if (i + 2 < T) load(i + 2);
        CP_ASYNC_COMMIT();
        CP_ASYNC_WAIT_2();
        __syncthreads();
        // Hazard-free with S=4/d=2 and a single barrier: all warps post-sync are
        // in iter i; writes hit stage (i+2)%4, reads hit i%4 -> disjoint.

        uint32_t abase = sb + (i % S) * STAGE;
        uint32_t bbase = abase + ABYTES;

#pragma unroll
        for (int kk = 0; kk < 4; kk++) {
            int coff = (kk * 16 + kg) * 2;
            uint32_t a[4][4], b[NT][4];
#pragma unroll
            for (int mi = 0; mi < 4; mi++) {
                int row = wm0 + mi * 16 + lrow8 + mg;
                uint32_t ad = abase + SMEM_SWIZZLE_128B((uint32_t)(row * 128 + coff));
                LDSM_X4(a[mi][0], a[mi][1], a[mi][2], a[mi][3], ad);
            }
#pragma unroll
            for (int nt = 0; nt < NT; nt++) {
                int row = wn0 + nt * 16 + lrow8 + mg;
                uint32_t bd = bbase + SMEM_SWIZZLE_128B((uint32_t)(row * 128 + coff));
                LDSM_X4(b[nt][0], b[nt][1], b[nt][2], b[nt][3], bd);
            }
#pragma unroll
            for (int mi = 0; mi < 4; mi++) {
#pragma unroll
                for (int nt = 0; nt < NT; nt++) {
                    MMA_BF16(acc[mi][nt * 2 + 0], a[mi], b[nt][0], b[nt][2]);
                    MMA_BF16(acc[mi][nt * 2 + 1], a[mi], b[nt][1], b[nt][3]);
                }
            }
        }
    }

    // ---------------- epilogue (registers only; no smem reuse) ----------------
    int qrow = lane >> 2;
    int qcol = (lane & 3) * 2;
#pragma unroll
    for (int mi = 0; mi < 4; mi++) {
#pragma unroll
        for (int ni = 0; ni < NI; ni++) {
#pragma unroll
            for (int h = 0; h < 2; h++) {
#pragma unroll
                for (int q = 0; q < 2; q++) {
                    int m = m0 + wm0 + mi * 16 + qrow + h * 8;
                    int n = n0 + wn0 + ni * 8 + qcol + q;
                    float v = acc[mi][ni][h * 2 + q] + bias[n];
                    if (EPI == 0) {
                        Cf[(size_t)m * Nout + n] = v;
                    } else if (EPI == 1) {
                        v += __bfloat162float(resid[(size_t)m * KIN + n])
                           + __bfloat162float(resid[(size_t)m * KIN + CC + n]);
                        split3a(v, Cb + (size_t)m * KIN, CC, n);
                    } else {
                        float rs = rsqrtf(bn_rv[n] + 1e-5f);
                        v = (v - bn_rm[n]) * rs * bn_w[n] + bn_b[n];
                        v = fmaxf(v, 0.f);
                        int bb = m / LL, l = m - bb * LL;
                        Cf[((size_t)bb * CC + n) * LL + l] = v;
                    }
                }
            }
        }
    }
}

// ---------------- x_proj ----------------
__global__ void xproj_kernel(const float* __restrict__ xpw)
{
    int idx = blockIdx.x * blockDim.x + threadIdx.x;
    if (idx >= MM * NPROJ) return;
    int m = idx / NPROJ, j = idx % NPROJ;
    const float* xr = g_xz + (size_t)m * DIN2;
    const float* wr = xpw + j * DD;
    float acc = 0.f;
#pragma unroll 8
    for (int k = 0; k < DD; k++) acc += xr[k] * wr[k];
    g_xdbl[idx] = acc;
}

// ---------------- dt softplus ----------------
__global__ void dt_kernel(const float* __restrict__ dtw)
{
    int idx = blockIdx.x * blockDim.x + threadIdx.x;
    if (idx >= MM * DD) return;
    int m = idx / DD, d = idx % DD;
    const float* xd = g_xdbl + (size_t)m * NPROJ;
    float acc = 0.f;
#pragma unroll
    for (int r = 0; r < RR; r++) acc += xd[r] * dtw[d * RR + r];
    float sp = (acc > 20.f) ? acc : log1pf(__expf(acc));
    g_dts[idx] = sp;
}

// ---------------- bidirectional scan + SiLU gate -> split-bf16 ssm ----------------
__global__ void scan_kernel(const float* __restrict__ A_logs,
                            const float* __restrict__ Ds)
{
    __shared__ float sB[LL][NN];
    __shared__ float sC[LL][NN];
    int b = blockIdx.x, d = threadIdx.x;

    for (int i = d; i < LL * 2 * NN; i += LL) {
        int l = i >> 5, j = i & 31;
        float v = g_xdbl[((size_t)(b * LL + l)) * NPROJ + RR + j];
        if (j < NN) sB[l][j] = v;
        else        sC[l][j - NN] = v;
    }
    __syncthreads();

    float Ar[NN];
#pragma unroll
    for (int n = 0; n < NN; n++) Ar[n] = -expf(A_logs[d * NN + n]);
    float Dd = Ds[d];

    float u[NN];
#pragma unroll
    for (int n = 0; n < NN; n++) u[n] = 0.f;

    for (int l = 0; l < LL; l++) {
        int m = b * LL + l;
        float dt = g_dts[(size_t)m * DD + d];
        float xv = g_xz [(size_t)m * DIN2 + d];
        float y = 0.f;
#pragma unroll
        for (int n = 0; n < NN; n++) {
            float a = __expf(dt * Ar[n]);
            u[n] = a * u[n] + dt * sB[l][n] * xv;
            y += u[n] * sC[l][n];
        }
        g_ssm[(size_t)m * DD + d] = y + Dd * xv;
    }

#pragma unroll
    for (int n = 0; n < NN; n++) u[n] = 0.f;
    for (int l = LL - 1; l >= 0; l--) {
        int m = b * LL + l;
        float dt = g_dts[(size_t)m * DD + d];
        float xv = g_xz [(size_t)m * DIN2 + d];
        float y = 0.f;
#pragma unroll
        for (int n = 0; n < NN; n++) {
            float a = __expf(dt * Ar[n]);
            u[n] = a * u[n] + dt * sB[l][n] * xv;
            y += u[n] * sC[l][n];
        }
        float tot = g_ssm[(size_t)m * DD + d] + y + Dd * xv;
        float z = g_xz[(size_t)m * DIN2 + DD + d];
        float sig = 1.f / (1.f + __expf(-z));
        split3a(tot * (z * sig), g_ssm_e + (size_t)m * KOUT, DD, d);
    }
}

// ---------------- launch ----------------
extern "C" void kernel_launch(void* const* d_in, const int* in_sizes, int n_in,
                              void* d_out, int out_size)
{
    const float* feat_map = (const float*)d_in[0];
    const float* ln_w     = (const float*)d_in[1];
    const float* ln_b     = (const float*)d_in[2];
    const float* in_w     = (const float*)d_in[3];
    const float* in_b     = (const float*)d_in[4];
    const float* x_proj_w = (const float*)d_in[5];
    const float* dt_w     = (const float*)d_in[6];
    const float* A_logs   = (const float*)d_in[7];
    const float* Ds       = (const float*)d_in[8];
    const float* out_w    = (const float*)d_in[9];
    const float* out_b    = (const float*)d_in[10];
    const float* mo_w     = (const float*)d_in[11];
    const float* mo_b     = (const float*)d_in[12];
    const float* bn_w     = (const float*)d_in[13];
    const float* bn_b     = (const float*)d_in[14];
    const float* bn_rm    = (const float*)d_in[15];
    const float* bn_rv    = (const float*)d_in[16];
    float* out = (float*)d_out;

    __nv_bfloat16 *fm_e, *out1_e, *ssm_e, *inw_e, *outw_e, *mow_e;
    float *xz;
    cudaGetSymbolAddress((void**)&fm_e,   g_fm_e);
    cudaGetSymbolAddress((void**)&out1_e, g_out1_e);
    cudaGetSymbolAddress((void**)&ssm_e,  g_ssm_e);
    cudaGetSymbolAddress((void**)&inw_e,  g_inw_e);
    cudaGetSymbolAddress((void**)&outw_e, g_outw_e);
    cudaGetSymbolAddress((void**)&mow_e,  g_mow_e);
    cudaGetSymbolAddress((void**)&xz,     g_xz);

    const int SMEM128 = 4 * (128 + 128) * 128;   // 131072
    const int SMEM256 = 4 * (128 + 256) * 128;   // 196608
    cudaFuncSetAttribute(gemm_mma<128, 0>, cudaFuncAttributeMaxDynamicSharedMemorySize, SMEM128);
    cudaFuncSetAttribute(gemm_mma<256, 1>, cudaFuncAttributeMaxDynamicSharedMemorySize, SMEM256);
    cudaFuncSetAttribute(gemm_mma<256, 2>, cudaFuncAttributeMaxDynamicSharedMemorySize, SMEM256);

    // 1. transpose + LN -> fm split-bf16 (activation layout)
    ln_kernel<<<MM, 256>>>(feat_map, ln_w, ln_b);

    // weight conversions (weight layout [h, h, lo])
    wconv_kernel<<<(DIN2 * CC + 255) / 256, 256>>>(in_w,  inw_e,  CC, DIN2 * CC);
    wconv_kernel<<<(CC * DD   + 255) / 256, 256>>>(out_w, outw_e, DD, CC * DD);
    wconv_kernel<<<(CC * CC   + 255) / 256, 256>>>(mo_w,  mow_e,  CC, CC * CC);

    // 2. in-projection: xz = fm @ in_w^T + in_b  (fp32 out)
    gemm_mma<128, 0><<<dim3(DIN2 / 128, MM / 128), 256, SMEM128>>>(
        fm_e, inw_e, KIN, DIN2, in_b, nullptr, xz, nullptr,
        nullptr, nullptr, nullptr, nullptr);

    // 3. x-proj + dt
    xproj_kernel<<<(MM * NPROJ + 255) / 256, 256>>>(x_proj_w);
    dt_kernel<<<(MM * DD) / 256, 256>>>(dt_w);

    // 4. scan + gate -> ssm split-bf16 (activation layout)
    scan_kernel<<<BSZ, DD>>>(A_logs, Ds);

    // 5. out-projection + fm residual -> out1 split-bf16 (activation layout)
    gemm_mma<256, 1><<<dim3(CC / 256, MM / 128), 256, SMEM256>>>(
        ssm_e, outw_e, KOUT, CC, out_b, fm_e, nullptr, out1_e,
        nullptr, nullptr, nullptr, nullptr);

    // 6. mixer GEMM + BN + ReLU + NCHW write
    gemm_mma<256, 2><<<dim3(CC / 256, MM / 128), 256, SMEM256>>>(
        out1_e, mow_e, KIN, CC, mo_b, nullptr, out, nullptr,
        bn_rm, bn_rv, bn_w, bn_b);
}